// round 5
// baseline (speedup 1.0000x reference)
#include <cuda_runtime.h>
#include <cuda_bf16.h>
#include <cstdint>

// PhysicsRouter, cp.async.bulk (TMA-class bulk copy) pipelined version.
// logits = X @ W^T + mass*bias; softmax; top-2; aux loss.
// X [16384, 4096] f32, mass [16384], W [4, 4096], bias [4].
// Output (f32): [0,65536) logits | [65536,98304) top_k_idx | [98304] aux | [98305,131073) top_k_w
//
// Block = 16 tokens, 256 threads. X streams through a 5-deep smem pipeline via
// cp.async.bulk + mbarrier (bulk copies have ~zero issue cost vs 16B cp.async
// whose LSU issue rate capped round 4 at 47% DRAM). Gate W stays L1-resident.

#define C_DIM 4096
#define E_DIM 4
#define N_TOK 16384
#define TPB 16                          // tokens per block
#define BLOCK_THREADS 256
#define NWARPS (BLOCK_THREADS / 32)     // 8
#define GRID_BLOCKS (N_TOK / TPB)       // 1024
#define STAGE_COLS 128
#define NSTAGES (C_DIM / STAGE_COLS)    // 32
#define DEPTH 5
#define STAGE_BYTES (TPB * STAGE_COLS * 4)   // 8192
#define ROW_BYTES (STAGE_COLS * 4)           // 512

__device__ float g_partial[GRID_BLOCKS][E_DIM];
__device__ unsigned int g_count = 0;    // wraps to 0 each full grid -> graph-replay safe

__device__ __forceinline__ uint32_t smem_u32(const void* p) {
    return (uint32_t)__cvta_generic_to_shared(p);
}
__device__ __forceinline__ void mbar_init(uint32_t a, uint32_t cnt) {
    asm volatile("mbarrier.init.shared.b64 [%0], %1;" :: "r"(a), "r"(cnt) : "memory");
}
__device__ __forceinline__ void mbar_expect_tx(uint32_t a, uint32_t bytes) {
    asm volatile("mbarrier.arrive.expect_tx.shared.b64 _, [%0], %1;"
                 :: "r"(a), "r"(bytes) : "memory");
}
__device__ __forceinline__ void bulk_g2s(uint32_t dst, const void* src,
                                         uint32_t bytes, uint32_t mb) {
    asm volatile(
        "cp.async.bulk.shared::cluster.global.mbarrier::complete_tx::bytes "
        "[%0], [%1], %2, [%3];"
        :: "r"(dst), "l"(src), "r"(bytes), "r"(mb) : "memory");
}
__device__ __forceinline__ void mbar_wait(uint32_t a, uint32_t parity) {
    asm volatile(
        "{\n\t"
        ".reg .pred P;\n\t"
        "WAIT_%=:\n\t"
        "mbarrier.try_wait.parity.acquire.cta.shared::cta.b64 P, [%0], %1, 0x989680;\n\t"
        "@P bra DONE_%=;\n\t"
        "bra WAIT_%=;\n\t"
        "DONE_%=:\n\t"
        "}"
        :: "r"(a), "r"(parity) : "memory");
}

__global__ __launch_bounds__(BLOCK_THREADS)
void router_bulk(const float* __restrict__ X,
                 const float* __restrict__ mass,
                 const float* __restrict__ W,
                 const float* __restrict__ bias,
                 float* __restrict__ out)
{
    __shared__ float sx[DEPTH][TPB][STAGE_COLS];          // 40 KB
    __shared__ alignas(8) unsigned long long mbar[DEPTH];
    __shared__ float s_imp[NWARPS][E_DIM];
    __shared__ bool  s_is_last;

    const int tid  = threadIdx.x;
    const int warp = tid >> 5;
    const int lane = tid & 31;
    const long token0 = (long)blockIdx.x * TPB;
    const float* xbase = X + token0 * (long)C_DIM;

    if (tid < DEPTH) mbar_init(smem_u32(&mbar[tid]), 1);
    __syncthreads();

    // ---- prologue: thread 0 launches DEPTH-1 stages ----
    if (tid == 0) {
#pragma unroll
        for (int s = 0; s < DEPTH - 1; s++) {
            const uint32_t mb = smem_u32(&mbar[s]);
            mbar_expect_tx(mb, STAGE_BYTES);
#pragma unroll
            for (int t = 0; t < TPB; t++) {
                bulk_g2s(smem_u32(&sx[s][t][0]),
                         xbase + (long)t * C_DIM + s * STAGE_COLS,
                         ROW_BYTES, mb);
            }
        }
    }

    // ---- mainloop ----
    const int t0 = warp * 2;
    float acc0[E_DIM] = {0.f, 0.f, 0.f, 0.f};
    float acc1[E_DIM] = {0.f, 0.f, 0.f, 0.f};

#pragma unroll 1
    for (int s = 0; s < NSTAGES; s++) {
        const int buf = s % DEPTH;
        mbar_wait(smem_u32(&mbar[buf]), (s / DEPTH) & 1);

        const int col = s * STAGE_COLS + lane * 4;
        float4 g[E_DIM];
#pragma unroll
        for (int e = 0; e < E_DIM; e++)
            g[e] = __ldg((const float4*)(W + e * C_DIM + col));   // L1-resident

        const float4 x0 = *(const float4*)&sx[buf][t0][lane * 4];
        const float4 x1 = *(const float4*)&sx[buf][t0 + 1][lane * 4];
#pragma unroll
        for (int e = 0; e < E_DIM; e++) {
            float a = acc0[e];
            a = fmaf(x0.x, g[e].x, a);
            a = fmaf(x0.y, g[e].y, a);
            a = fmaf(x0.z, g[e].z, a);
            a = fmaf(x0.w, g[e].w, a);
            acc0[e] = a;
            float b = acc1[e];
            b = fmaf(x1.x, g[e].x, b);
            b = fmaf(x1.y, g[e].y, b);
            b = fmaf(x1.z, g[e].z, b);
            b = fmaf(x1.w, g[e].w, b);
            acc1[e] = b;
        }

        __syncthreads();       // all threads done reading buf before it is refilled

        const int ns = s + DEPTH - 1;
        if (tid == 0 && ns < NSTAGES) {
            const int nb = ns % DEPTH;
            const uint32_t mb = smem_u32(&mbar[nb]);
            mbar_expect_tx(mb, STAGE_BYTES);
#pragma unroll
            for (int t = 0; t < TPB; t++) {
                bulk_g2s(smem_u32(&sx[nb][t][0]),
                         xbase + (long)t * C_DIM + ns * STAGE_COLS,
                         ROW_BYTES, mb);
            }
        }
    }

    // ---- butterfly reduce both tokens' accumulators across the warp ----
#pragma unroll
    for (int e = 0; e < E_DIM; e++) {
#pragma unroll
        for (int s = 16; s > 0; s >>= 1) {
            acc0[e] += __shfl_xor_sync(0xFFFFFFFFu, acc0[e], s);
            acc1[e] += __shfl_xor_sync(0xFFFFFFFFu, acc1[e], s);
        }
    }

    // ---- epilogue: lane 0 of each warp handles its 2 tokens ----
    if (lane == 0) {
        const float4 b = __ldg((const float4*)bias);
        float psum[E_DIM];
#pragma unroll
        for (int e = 0; e < E_DIM; e++) psum[e] = 0.0f;

#pragma unroll
        for (int k = 0; k < 2; k++) {
            const long token = token0 + t0 + k;
            float q0 = k ? acc1[0] : acc0[0];
            float q1 = k ? acc1[1] : acc0[1];
            float q2 = k ? acc1[2] : acc0[2];
            float q3 = k ? acc1[3] : acc0[3];

            const float m = __ldg(mass + token);
            q0 = fmaf(m, b.x, q0);
            q1 = fmaf(m, b.y, q1);
            q2 = fmaf(m, b.z, q2);
            q3 = fmaf(m, b.w, q3);

            float4 lo; lo.x = q0; lo.y = q1; lo.z = q2; lo.w = q3;
            *(float4*)(out + token * E_DIM) = lo;

            const float mx = fmaxf(fmaxf(q0, q1), fmaxf(q2, q3));
            float p[E_DIM];
            p[0] = expf(q0 - mx);
            p[1] = expf(q1 - mx);
            p[2] = expf(q2 - mx);
            p[3] = expf(q3 - mx);
            const float inv = 1.0f / (p[0] + p[1] + p[2] + p[3]);
#pragma unroll
            for (int e = 0; e < E_DIM; e++) { p[e] *= inv; psum[e] += p[e]; }

            // top-2, lowest-index tie break (strict > keeps earlier index)
            int i1 = 0; float v1 = p[0];
#pragma unroll
            for (int e = 1; e < E_DIM; e++)
                if (p[e] > v1) { v1 = p[e]; i1 = e; }
            int i2 = -1; float v2 = -1.0f;
#pragma unroll
            for (int e = 0; e < E_DIM; e++)
                if (e != i1 && p[e] > v2) { v2 = p[e]; i2 = e; }

            float* out_idx = out + (long)N_TOK * E_DIM;
            float* out_w   = out + (long)N_TOK * E_DIM + (long)N_TOK * 2 + 1;
            out_idx[token * 2 + 0] = (float)i1;
            out_idx[token * 2 + 1] = (float)i2;
            out_w[token * 2 + 0]   = v1;
            out_w[token * 2 + 1]   = v2;
        }

#pragma unroll
        for (int e = 0; e < E_DIM; e++) s_imp[warp][e] = psum[e];
    }
    __syncthreads();

    if (tid == 0) {
        float pb[E_DIM] = {0.f, 0.f, 0.f, 0.f};
#pragma unroll
        for (int w = 0; w < NWARPS; w++)
#pragma unroll
            for (int e = 0; e < E_DIM; e++) pb[e] += s_imp[w][e];
#pragma unroll
        for (int e = 0; e < E_DIM; e++) g_partial[blockIdx.x][e] = pb[e];
        __threadfence();
        const unsigned int v = atomicInc(&g_count, GRID_BLOCKS - 1);
        s_is_last = (v == GRID_BLOCKS - 1);
    }
    __syncthreads();

    // ---- last block finalizes aux loss ----
    if (s_is_last) {
        __shared__ double s_sum[BLOCK_THREADS];
        const int e = tid & 3;
        const int chunk = tid >> 2;                           // 0..63
        const int per = GRID_BLOCKS / (BLOCK_THREADS / 4);    // 16
        double s = 0.0;
        for (int j = chunk * per; j < (chunk + 1) * per; j++)
            s += (double)g_partial[j][e];
        s_sum[tid] = s;
        __syncthreads();
        if (tid < E_DIM) {
            double imp = 0.0;
#pragma unroll
            for (int k = 0; k < BLOCK_THREADS / 4; k++)
                imp += s_sum[e + 4 * k];                      // e == tid here
            s_sum[tid] = imp;
        }
        __syncthreads();
        if (tid == 0) {
            const double target = (double)N_TOK / (double)E_DIM;
            double loss = 0.0;
#pragma unroll
            for (int k = 0; k < E_DIM; k++) {
                const double d = s_sum[k] - target;
                loss += d * d;
            }
            out[(long)N_TOK * E_DIM + (long)N_TOK * 2] = (float)(loss / E_DIM);
        }
    }
}

extern "C" void kernel_launch(void* const* d_in, const int* in_sizes, int n_in,
                              void* d_out, int out_size)
{
    const float* X    = (const float*)d_in[0];
    const float* mass = (const float*)d_in[1];
    const float* W    = (const float*)d_in[2];
    const float* bias = (const float*)d_in[3];
    float* out = (float*)d_out;

    router_bulk<<<GRID_BLOCKS, BLOCK_THREADS>>>(X, mass, W, bias, out);
}